// round 2
// baseline (speedup 1.0000x reference)
#include <cuda_runtime.h>
#include <cuda_bf16.h>
#include <cstdint>

// One-hot expansion: mask [1,1,256,256,48] fp32 integer labels 0..40
//   -> out [1,40,256,256,48], out[:,c] = (mask == c+1) ? 1.0f : 0.0f
//
// Pure streaming-store bound (503 MB writes, 12.6 MB reads).
// Each thread handles 8 consecutive spatial floats (2 x float4) and writes
// 2 float4 per channel with evict-first (.cs) streaming hints, so a warp
// emits 1024B contiguous per channel (8 full 128B lines) and the output
// stream does not pollute L2.

#define N_LABELS 40

__global__ __launch_bounds__(256)
void onehot40_kernel(const float4* __restrict__ mask4,
                     float4* __restrict__ out4,
                     int vol4) {
    // each thread owns float4 pair (2*i, 2*i+1)
    int t = blockIdx.x * blockDim.x + threadIdx.x;
    int i0 = 2 * t;
    if (i0 >= vol4) return;

    float4 ma = __ldcs(&mask4[i0]);
    float4 mb = __ldcs(&mask4[i0 + 1]);

#pragma unroll
    for (int c = 0; c < N_LABELS; c++) {
        const float lab = (float)(c + 1);
        float4 ra, rb;
        ra.x = (ma.x == lab) ? 1.0f : 0.0f;
        ra.y = (ma.y == lab) ? 1.0f : 0.0f;
        ra.z = (ma.z == lab) ? 1.0f : 0.0f;
        ra.w = (ma.w == lab) ? 1.0f : 0.0f;
        rb.x = (mb.x == lab) ? 1.0f : 0.0f;
        rb.y = (mb.y == lab) ? 1.0f : 0.0f;
        rb.z = (mb.z == lab) ? 1.0f : 0.0f;
        rb.w = (mb.w == lab) ? 1.0f : 0.0f;
        size_t base = (size_t)c * (size_t)vol4 + (size_t)i0;
        __stcs(&out4[base],     ra);
        __stcs(&out4[base + 1], rb);
    }
}

extern "C" void kernel_launch(void* const* d_in, const int* in_sizes, int n_in,
                              void* d_out, int out_size) {
    const float* mask = (const float*)d_in[0];
    float* out = (float*)d_out;

    int vol = in_sizes[0];          // 3,145,728 (divisible by 8)
    int vol4 = vol / 4;             // 786,432
    int nthreads_total = vol / 8;   // 393,216 threads, each does 2 float4

    int threads = 256;
    int blocks = (nthreads_total + threads - 1) / threads;

    onehot40_kernel<<<blocks, threads>>>(
        (const float4*)mask, (float4*)out, vol4);
}

// round 6
// speedup vs baseline: 1.6730x; 1.6730x over previous
#include <cuda_runtime.h>
#include <cuda_bf16.h>
#include <cstdint>

// One-hot expansion: mask [1,1,256,256,48] fp32 integer labels 0..40
//   -> out [1,40,256,256,48], out[:,c] = (mask == c+1) ? 1.0f : 0.0f
//
// Pure streaming-store bound (503 MB writes, 12.6 MB reads).
// R1 layout (thread t owns float4 t: each warp STG.128 covers a contiguous
// 512B span = 4 full lines) + evict-first streaming hints so the output
// stream doesn't pollute L2. R2 showed per-thread multi-float4 striding
// doubles L1 wavefronts per store — reverted.
// (R3/R4/R5 runs failed at the container/broker level before this code ran;
//  clean re-bench of the same source.)

#define N_LABELS 40

__global__ __launch_bounds__(256)
void onehot40_kernel(const float4* __restrict__ mask4,
                     float4* __restrict__ out4,
                     int vol4) {
    int i = blockIdx.x * blockDim.x + threadIdx.x;
    if (i >= vol4) return;

    float4 m = __ldcs(&mask4[i]);

#pragma unroll
    for (int c = 0; c < N_LABELS; c++) {
        const float lab = (float)(c + 1);
        float4 r;
        r.x = (m.x == lab) ? 1.0f : 0.0f;
        r.y = (m.y == lab) ? 1.0f : 0.0f;
        r.z = (m.z == lab) ? 1.0f : 0.0f;
        r.w = (m.w == lab) ? 1.0f : 0.0f;
        __stcs(&out4[(size_t)c * (size_t)vol4 + (size_t)i], r);
    }
}

extern "C" void kernel_launch(void* const* d_in, const int* in_sizes, int n_in,
                              void* d_out, int out_size) {
    const float* mask = (const float*)d_in[0];
    float* out = (float*)d_out;

    int vol = in_sizes[0];          // 256*256*48 = 3,145,728 (divisible by 4)
    int vol4 = vol / 4;             // 786,432

    int threads = 256;
    int blocks = (vol4 + threads - 1) / threads;

    onehot40_kernel<<<blocks, threads>>>(
        (const float4*)mask, (float4*)out, vol4);
}